// round 16
// baseline (speedup 1.0000x reference)
#include <cuda_runtime.h>
#include <cuda_fp16.h>
#include <math.h>
#include <stdint.h>

#define N_B 4
#define L_S 4096
#define EMB 128
#define H_N 4
#define D_H 32
#define C1 0.12751744766f       /* (1/sqrt(128)) * log2(e) */
#define MASKF (-3.0e38f)

#define TM 128
#define TK 128
#define NKT (L_S/TK)
#define NH (N_B*H_N)

#define PSQ 2048               /* QK image: 4 d-octet planes of [128 rows][16B] */
#define PSV 512                /* V image: 16 key-octet planes of [32 d][16B]   */
#define TILE_U4 512            /* 8192 bytes per tile image */

/* fused kernel smem: 3 stages x (Kh 8K + Vt 8K) + Q (8K) + fp32 bias (16K) */
#define F_STGSZ 16384
#define F_Q    (3*F_STGSZ)
#define F_BIAS (F_Q + 8192)
#define SMEM_FUSED (F_BIAS + 16384)

/* ---------------- scratch ---------------- */
__device__ float g_O[NH*L_S*D_H];
__device__ uint4 g_imgQh[NH*NKT*TILE_U4];
__device__ uint4 g_imgKh[NH*NKT*TILE_U4];
__device__ uint4 g_imgVt[NH*NKT*TILE_U4];

/* ---------------- helpers ---------------- */
__device__ __forceinline__ uint32_t smem_u32(const void* p){
    uint32_t a;
    asm("{ .reg .u64 t; cvta.to.shared.u64 t, %1; cvt.u32.u64 %0, t; }" : "=r"(a) : "l"(p));
    return a;
}
__device__ __forceinline__ void mma_f16(float* c, const uint32_t* a, const uint32_t* b){
    asm volatile("mma.sync.aligned.m16n8k16.row.col.f32.f16.f16.f32 "
        "{%0,%1,%2,%3}, {%4,%5,%6,%7}, {%8,%9}, {%0,%1,%2,%3};"
        : "+f"(c[0]), "+f"(c[1]), "+f"(c[2]), "+f"(c[3])
        : "r"(a[0]), "r"(a[1]), "r"(a[2]), "r"(a[3]), "r"(b[0]), "r"(b[1]));
}
#define LDMX4(r, a) \
    asm volatile("ldmatrix.sync.aligned.m8n8.x4.shared.b16 {%0,%1,%2,%3}, [%4];" \
        : "=r"((r)[0]), "=r"((r)[1]), "=r"((r)[2]), "=r"((r)[3]) : "r"(a))
#define CPA16(dst, src) \
    asm volatile("cp.async.cg.shared.global [%0], [%1], 16;" :: "r"(dst), "l"(src))
#define CPA_COMMIT() asm volatile("cp.async.commit_group;" ::: "memory")
#define CPA_WAIT(n)  asm volatile("cp.async.wait_group %0;" :: "n"(n) : "memory")

__device__ __forceinline__ float ex2a(float x){
    float r;
    asm("ex2.approx.f32 %0, %1;" : "=f"(r) : "f"(x));
    return r;
}
__device__ __forceinline__ uint32_t h2bits(__half2 v){
    return *reinterpret_cast<uint32_t*>(&v);
}

__device__ __forceinline__ void q_frags(uint32_t base, int wr, int lane, uint32_t qf[2][4])
{
    int m = lane >> 3;
    int row = wr + (m & 1)*8 + (lane & 7);
    uint32_t a0 = base + (m >> 1)*PSQ + row*16;
    LDMX4(qf[0], a0);
    LDMX4(qf[1], a0 + 2*PSQ);
}

/* ------- kernel 1: fused projection + fp16 image build ------- */
/* grid (NKT, NH, 3): z selects Q / K / V */
__global__ __launch_bounds__(256) void projconv_kernel(
    const float* __restrict__ vin, const float* __restrict__ kin,
    const float* __restrict__ qin,
    const float* __restrict__ Wv, const float* __restrict__ Wk,
    const float* __restrict__ Wq)
{
    __shared__ float Ws[D_H*33];
    __shared__ float Xs[128*33];
    int t = threadIdx.x;
    int kt = blockIdx.x, nh = blockIdx.y, mm = blockIdx.z;
    int n = nh >> 2, h = nh & 3;
    size_t inbase = ((size_t)n*L_S + (size_t)kt*128)*EMB + h*D_H;
    size_t ti = (size_t)(nh*NKT + kt) * TILE_U4;

    const float* in = (mm == 0) ? qin : (mm == 1 ? kin : vin);
    const float* W  = (mm == 0) ? Wq  : (mm == 1 ? Wk  : Wv);

    for (int i = t; i < D_H*D_H; i += 256) {
        int e = i >> 5, d = i & 31;
        Ws[e*33+d] = W[i];
    }
    for (int idx = t; idx < 128*8; idx += 256) {
        int rr = idx >> 3, c4 = idx & 7;
        float4 x = *(const float4*)&in[inbase + (size_t)rr*EMB + c4*4];
        float* drow = &Xs[rr*33 + c4*4];
        drow[0] = x.x; drow[1] = x.y; drow[2] = x.z; drow[3] = x.w;
    }
    __syncthreads();

    int r = t & 127, half = t >> 7;
    int e0 = half*16;

    float x[D_H];
    #pragma unroll
    for (int d = 0; d < D_H; d++) x[d] = Xs[r*33 + d];

    float o[16];
    #pragma unroll
    for (int j = 0; j < 16; j++) {
        float a = 0.f;
        const float* wrow = &Ws[(e0+j)*33];
        #pragma unroll
        for (int d = 0; d < D_H; d++) a = fmaf(x[d], wrow[d], a);
        o[j] = a;
    }

    if (mm < 2) {
        uint32_t hw[8];
        #pragma unroll
        for (int j = 0; j < 8; j++)
            hw[j] = h2bits(__floats2half2_rn(o[2*j], o[2*j+1]));
        uint4* dst = (mm == 0 ? g_imgQh : g_imgKh) + ti;
        int oct0 = half*2;
        dst[(oct0  )*128 + r] = make_uint4(hw[0], hw[1], hw[2], hw[3]);
        dst[(oct0+1)*128 + r] = make_uint4(hw[4], hw[5], hw[6], hw[7]);
    } else {
        __syncthreads();      /* everyone's x regs loaded before overwrite */
        float* drow = &Xs[r*33 + e0];
        #pragma unroll
        for (int j = 0; j < 16; j++) drow[j] = o[j];
        __syncthreads();
        #pragma unroll
        for (int i = 0; i < 2; i++) {
            int item = t + i*256;
            int oct = item >> 5, d = item & 31;
            uint32_t w2v[4];
            #pragma unroll
            for (int w2 = 0; w2 < 4; w2++) {
                float x0 = Xs[(oct*8 + w2*2)*33 + d];
                float x1 = Xs[(oct*8 + w2*2 + 1)*33 + d];
                w2v[w2] = h2bits(__floats2half2_rn(x0, x1));
            }
            g_imgVt[ti + item] = make_uint4(w2v[0], w2v[1], w2v[2], w2v[3]);
        }
    }
}

/* ------- kernel 2: fused rowsum + attn_w + O = P @ V ------- */
__global__ __launch_bounds__(256, 3) void fused_kernel(const int* __restrict__ mask,
                                                       float* __restrict__ attn_out,
                                                       int write_attn)
{
    extern __shared__ char smem[];
    uint32_t sb = smem_u32(smem);
    int t = threadIdx.x, lane = t & 31, w = t >> 5;
    int gid = lane >> 2, cp = (lane & 3)*2, wr = w*16;
    int nh = blockIdx.y, n = nh >> 2, qt = blockIdx.x, qr0 = qt * TM;
    const int* mrow = mask + n*L_S;
    float* bias = (float*)(smem + F_BIAS);
    float* Ag = attn_out ? attn_out + (size_t)nh*L_S*L_S : (float*)0;

    const uint4* Qh = g_imgQh + (size_t)(nh*NKT + qt)*TILE_U4;
    const uint4* Kh = g_imgKh + (size_t)nh*NKT*TILE_U4;
    const uint4* Vt = g_imgVt + (size_t)nh*NKT*TILE_U4;

    int kq = lane >> 3;
    uint32_t koff = kq*PSQ + (lane&7)*16;
    uint32_t voff = (kq & 1)*PSV + ((kq >> 1)*8 + (lane&7))*16;

    /* ---- prologue: group0 = Q + K0, group1 = K1; bias build ---- */
    #pragma unroll
    for (int i = 0; i < 2; i++) {
        int it2 = t + i*256;
        CPA16(sb + F_Q + it2*16, Qh + it2);
        CPA16(sb +       it2*16, Kh + it2);
    }
    CPA_COMMIT();
    {
        const uint4* src = Kh + TILE_U4;
        CPA16(sb + F_STGSZ + t*16,        src + t);
        CPA16(sb + F_STGSZ + (t+256)*16,  src + t + 256);
    }
    CPA_COMMIT();
    #pragma unroll
    for (int i = 0; i < 16; i++) {
        int idx = t + i*256;
        bias[idx] = mrow[idx] ? 0.f : MASKF;
    }
    CPA_WAIT(1);                 /* group0 (Q + K0) complete */
    __syncthreads();

    uint32_t qh[2][4];
    q_frags(sb + F_Q, wr, lane, qh);

    /* ---- phase 1: row sums, prefetch distance 2 ---- */
    float sum0 = 0.f, sum1 = 0.f;

    for (int kt = 0; kt < NKT; kt++) {
        if (kt) {
            if (kt < NKT-1) { CPA_WAIT(1); } else { CPA_WAIT(0); }
            __syncthreads();
        }
        /* prefetch kt+2 (stage reuse is safe: sync above covers readers of this stage) */
        if (kt + 2 < NKT) {
            uint32_t st = sb + ((kt+2)%3)*F_STGSZ;
            const uint4* src = Kh + (size_t)(kt+2)*TILE_U4;
            CPA16(st + t*16, src + t);
            CPA16(st + (t+256)*16, src + t + 256);
        }
        CPA_COMMIT();

        uint32_t kb = sb + (kt%3)*F_STGSZ + koff;
        const float* bk = bias + kt*TK;

        #pragma unroll 8
        for (int pj = 0; pj < 8; pj++) {
            uint32_t k0[4], k1[4];
            LDMX4(k0, kb + (pj*2)*128);
            LDMX4(k1, kb + (pj*2+1)*128);
            float c0[4] = {0.f,0.f,0.f,0.f};
            float c1[4] = {0.f,0.f,0.f,0.f};
            mma_f16(c0, qh[0], k0);
            mma_f16(c1, qh[0], k1);
            mma_f16(c0, qh[1], k0 + 2);
            mma_f16(c1, qh[1], k1 + 2);

            float2 ba = *(const float2*)&bk[pj*16 + cp];
            float2 bb = *(const float2*)&bk[pj*16 + 8 + cp];
            sum0 += ex2a(fmaf(c0[0], C1, ba.x)) + ex2a(fmaf(c0[1], C1, ba.y))
                  + ex2a(fmaf(c1[0], C1, bb.x)) + ex2a(fmaf(c1[1], C1, bb.y));
            sum1 += ex2a(fmaf(c0[2], C1, ba.x)) + ex2a(fmaf(c0[3], C1, ba.y))
                  + ex2a(fmaf(c1[2], C1, bb.x)) + ex2a(fmaf(c1[3], C1, bb.y));
        }
    }
    __syncthreads();             /* all phase-1 reads complete before stage reuse */

    /* ---- phase-2 prologue: groups H0 (K0+V0), H1 (K1+V1); overlap reduction ---- */
    #pragma unroll
    for (int i = 0; i < 2; i++) {
        int it2 = t + i*256;
        CPA16(sb +        it2*16, Kh + it2);
        CPA16(sb + 8192 + it2*16, Vt + it2);
    }
    CPA_COMMIT();
    {
        size_t ti = (size_t)TILE_U4;
        #pragma unroll
        for (int i = 0; i < 2; i++) {
            int it2 = t + i*256;
            CPA16(sb + F_STGSZ + it2*16,        Kh + ti + it2);
            CPA16(sb + F_STGSZ + 8192 + it2*16, Vt + ti + it2);
        }
    }
    CPA_COMMIT();

    sum0 += __shfl_xor_sync(0xffffffffu, sum0, 1);
    sum0 += __shfl_xor_sync(0xffffffffu, sum0, 2);
    sum1 += __shfl_xor_sync(0xffffffffu, sum1, 1);
    sum1 += __shfl_xor_sync(0xffffffffu, sum1, 2);
    float nls0 = -__log2f(sum0);
    float nls1 = -__log2f(sum1);

    /* ---- phase 2: recompute S, write attn_w, P@V; prefetch distance 2 ---- */
    float o[4][4];
    #pragma unroll
    for (int jd = 0; jd < 4; jd++)
        #pragma unroll
        for (int i = 0; i < 4; i++) o[jd][i] = 0.f;

    float* Arow0 = Ag ? Ag + (size_t)(qr0 + wr + gid)*L_S : (float*)0;
    float* Arow1 = Ag ? Ag + (size_t)(qr0 + wr + gid + 8)*L_S : (float*)0;

    for (int kt = 0; kt < NKT; kt++) {
        if (kt < NKT-1) { CPA_WAIT(1); } else { CPA_WAIT(0); }
        __syncthreads();

        if (kt + 2 < NKT) {
            uint32_t st = sb + ((kt+2)%3)*F_STGSZ;
            size_t ti = (size_t)(kt+2)*TILE_U4;
            #pragma unroll
            for (int i = 0; i < 2; i++) {
                int it2 = t + i*256;
                CPA16(st + it2*16,        Kh + ti + it2);
                CPA16(st + 8192 + it2*16, Vt + ti + it2);
            }
        }
        CPA_COMMIT();

        uint32_t stg = sb + (kt%3)*F_STGSZ;
        uint32_t kbh = stg + koff;
        uint32_t vb0 = stg + 8192 + voff;
        const float* bk = bias + kt*TK;
        float* a0 = Arow0 ? Arow0 + kt*TK + cp : (float*)0;
        float* a1 = Arow1 ? Arow1 + kt*TK + cp : (float*)0;

        #pragma unroll 4
        for (int pj = 0; pj < 8; pj++) {
            uint32_t k0[4], k1[4];
            LDMX4(k0, kbh + (pj*2)*128);
            LDMX4(k1, kbh + (pj*2+1)*128);

            float c0[4] = {0.f,0.f,0.f,0.f};
            float c1[4] = {0.f,0.f,0.f,0.f};
            mma_f16(c0, qh[0], k0);
            mma_f16(c1, qh[0], k1);
            mma_f16(c0, qh[1], k0 + 2);
            mma_f16(c1, qh[1], k1 + 2);

            float2 ba = *(const float2*)&bk[pj*16 + cp];
            float2 bb = *(const float2*)&bk[pj*16 + 8 + cp];
            float p0 = ex2a(fmaf(c0[0], C1, nls0 + ba.x));
            float p1 = ex2a(fmaf(c0[1], C1, nls0 + ba.y));
            float p2 = ex2a(fmaf(c0[2], C1, nls1 + ba.x));
            float p3 = ex2a(fmaf(c0[3], C1, nls1 + ba.y));
            float p4 = ex2a(fmaf(c1[0], C1, nls0 + bb.x));
            float p5 = ex2a(fmaf(c1[1], C1, nls0 + bb.y));
            float p6 = ex2a(fmaf(c1[2], C1, nls1 + bb.x));
            float p7 = ex2a(fmaf(c1[3], C1, nls1 + bb.y));

            if (write_attn) {
                /* streaming stores: keep attn_w out of L2 (evict-first) */
                __stcs((float2*)&a0[pj*16],     make_float2(p0, p1));
                __stcs((float2*)&a1[pj*16],     make_float2(p2, p3));
                __stcs((float2*)&a0[pj*16 + 8], make_float2(p4, p5));
                __stcs((float2*)&a1[pj*16 + 8], make_float2(p6, p7));
            }

            uint32_t ah[4];
            ah[0] = h2bits(__floats2half2_rn(p0, p1));
            ah[1] = h2bits(__floats2half2_rn(p2, p3));
            ah[2] = h2bits(__floats2half2_rn(p4, p5));
            ah[3] = h2bits(__floats2half2_rn(p6, p7));

            uint32_t va[4], vb2[4];
            LDMX4(va,  vb0 + (2*pj)*PSV);
            LDMX4(vb2, vb0 + (2*pj)*PSV + 256);

            mma_f16(o[0], ah, va);
            mma_f16(o[1], ah, va + 2);
            mma_f16(o[2], ah, vb2);
            mma_f16(o[3], ah, vb2 + 2);
        }
    }

    float* Og0 = g_O + (size_t)(nh*L_S + qr0 + wr + gid)*D_H;
    float* Og1 = g_O + (size_t)(nh*L_S + qr0 + wr + gid + 8)*D_H;
    #pragma unroll
    for (int jd = 0; jd < 4; jd++) {
        int col = jd*8 + cp;
        __stcs((float2*)&Og0[col], make_float2(o[jd][0], o[jd][1]));
        __stcs((float2*)&Og1[col], make_float2(o[jd][2], o[jd][3]));
    }
}

/* ------- kernel 3: out = concat(O) @ Wo^T + bo (register-tiled) ------- */
#define OP_PITCH 132
__global__ __launch_bounds__(256) void outproj_kernel(const float* __restrict__ Wo,
                                                      const float* __restrict__ bo,
                                                      float* __restrict__ out)
{
    __shared__ float Xs[64*OP_PITCH];
    __shared__ float Wsm[64*OP_PITCH];
    int t = threadIdx.x;
    int row0 = blockIdx.x * 64;
    int eg = t & 7;
    int rt = t >> 3;

    for (int idx = t; idx < 64*32; idx += 256) {
        int r = idx >> 5, c4 = idx & 31;
        int row = row0 + r;
        int n = row >> 12, l = row & 4095;
        int f0 = c4*4;
        float4 v = make_float4(
            g_O[(((size_t)n*H_N + (f0>>5))*L_S + l)*D_H + (f0 & 31)],
            g_O[(((size_t)n*H_N + ((f0+1)>>5))*L_S + l)*D_H + ((f0+1) & 31)],
            g_O[(((size_t)n*H_N + ((f0+2)>>5))*L_S + l)*D_H + ((f0+2) & 31)],
            g_O[(((size_t)n*H_N + ((f0+3)>>5))*L_S + l)*D_H + ((f0+3) & 31)]);
        *(float4*)&Xs[r*OP_PITCH + f0] = v;
    }

    for (int et = 0; et < 2; et++) {
        __syncthreads();
        for (int idx = t; idx < 64*32; idx += 256) {
            int e = idx >> 5, c4 = idx & 31;
            *(float4*)&Wsm[e*OP_PITCH + c4*4] =
                *(const float4*)&Wo[(size_t)(et*64 + e)*EMB + c4*4];
        }
        __syncthreads();

        float acc[2][8];
        #pragma unroll
        for (int r = 0; r < 2; r++)
            #pragma unroll
            for (int j = 0; j < 8; j++) acc[r][j] = 0.f;

        const float* x0 = &Xs[(rt*2)*OP_PITCH];
        const float* x1 = &Xs[(rt*2+1)*OP_PITCH];
        #pragma unroll 4
        for (int f = 0; f < EMB; f++) {
            float a0 = x0[f], a1 = x1[f];
            #pragma unroll
            for (int j = 0; j < 8; j++) {
                float wv = Wsm[(j*8 + eg)*OP_PITCH + f];
                acc[0][j] += a0 * wv;
                acc[1][j] += a1 * wv;
            }
        }

        #pragma unroll
        for (int r = 0; r < 2; r++) {
            int row = row0 + rt*2 + r;
            #pragma unroll
            for (int j = 0; j < 8; j++) {
                int e = et*64 + j*8 + eg;
                out[(size_t)row*EMB + e] = acc[r][j] + bo[e];
            }
        }
    }
}

/* ---------------- launch ---------------- */
extern "C" void kernel_launch(void* const* d_in, const int* in_sizes, int n_in,
                              void* d_out, int out_size)
{
    const float* values = (const float*)d_in[0];
    const float* keys   = (const float*)d_in[1];
    const float* query  = (const float*)d_in[2];
    const int*   mask   = (const int*)d_in[3];
    const float* Wv     = (const float*)d_in[4];
    const float* Wk     = (const float*)d_in[5];
    const float* Wq     = (const float*)d_in[6];
    const float* Wo     = (const float*)d_in[7];
    const float* bo     = (const float*)d_in[8];
    float* out = (float*)d_out;

    const long long out_elems  = (long long)N_B * L_S * EMB;
    const long long attn_elems = (long long)N_B * H_N * L_S * L_S;
    int has_attn = ((long long)out_size >= out_elems + attn_elems);
    float* attn_out = has_attn ? (out + out_elems) : (float*)0;

    cudaFuncSetAttribute(fused_kernel, cudaFuncAttributeMaxDynamicSharedMemorySize, SMEM_FUSED);

    dim3 gc(NKT, NH, 3);
    projconv_kernel<<<gc, 256>>>(values, keys, query, Wv, Wk, Wq);

    dim3 g(L_S/TM, NH);
    fused_kernel<<<g, 256, SMEM_FUSED>>>(mask, attn_out, has_attn);

    outproj_kernel<<<(N_B*L_S)/64, 256>>>(Wo, bo, out);
}